// round 14
// baseline (speedup 1.0000x reference)
#include <cuda_runtime.h>
#include <cuda_fp16.h>
#include <cstdint>

// ---------------------------------------------------------------------------
// SimpleCnn: conv1(3->64)+leaky+pool -> conv2(64->64)+leaky+pool -> FC
// conv1: fp16 m16n8k16, K reindexed k=tap*4+ic so A-pairs are pre-packed
//        in smem (one LDS.32 per fragment, no pack_hh in mainloop).
// conv2: fp16 m16n8k16, cp.async double-buffered (R13-proven).
// FC: two-pass deterministic, 4 batches per block.
// ---------------------------------------------------------------------------

#define NB   32
#define OCH  64
#define HB   112
#define HC   56
#define FLATK (OCH*HC*HC)   // 200704
#define NCHUNK 98
#define CHUNK  2048

__device__ uint32_t g_h1h[NB*32*HB*HB];       // half2 pairs, 51.4 MB
__device__ float    g_h2[NB*OCH*HC*HC];       // 25.7 MB
__device__ float    g_fcp[NCHUNK*8*40];
__device__ __align__(16) uint32_t g_zero[8];  // zero-init, cp.async OOB source

__device__ __forceinline__ uint32_t pack_h2(float a, float b) {
    __half2 h = __floats2half2_rn(a, b);
    return *reinterpret_cast<uint32_t*>(&h);
}

__device__ __forceinline__ void mma_f16(float* c,
                                        uint32_t a0, uint32_t a1, uint32_t a2, uint32_t a3,
                                        uint32_t b0, uint32_t b1) {
    asm volatile("mma.sync.aligned.m16n8k16.row.col.f32.f16.f16.f32 "
                 "{%0,%1,%2,%3}, {%4,%5,%6,%7}, {%8,%9}, {%0,%1,%2,%3};"
                 : "+f"(c[0]), "+f"(c[1]), "+f"(c[2]), "+f"(c[3])
                 : "r"(a0), "r"(a1), "r"(a2), "r"(a3), "r"(b0), "r"(b1));
}

#define CP_ASYNC16(dst, src) \
    asm volatile("cp.async.cg.shared.global [%0], [%1], 16;" :: "r"(dst), "l"(src))
#define CP_COMMIT() asm volatile("cp.async.commit_group;")
#define CP_WAIT(N)  asm volatile("cp.async.wait_group %0;" :: "n"(N))

__global__ void nop_kernel() {}

// ---------------------------------------------------------------------------
// conv1: x -> h1h (packed half2 oc-pairs).
// K-order: k = tap*4 + ic (ic padded to 4). pair p = (k=2p, 2p+1):
//   tap = p>>1, half h = p&1: h=0 -> (ic0,ic1), h=1 -> (ic2, 0).
// 3 k16 chunks (pairs 8c..8c+7 = taps 4c..4c+3); taps>=9 are zero pairs.
// Block: (b, pooled row). 448 thr = 14 warps, warp = 16-col strip.
// ---------------------------------------------------------------------------
#define HOFF 944     // h-array stride (4*232 + 16 pad: shifts banks by 16)

__global__ void __launch_bounds__(448, 1)
conv1_mma(const float* __restrict__ x,
          const float* __restrict__ w1,
          const float* __restrict__ bias,
          uint32_t* __restrict__ outp)
{
    __shared__ uint32_t s_p[2*HOFF];   // [h][row stride232][col 0..225] u32 pairs
    __shared__ uint32_t s_w[64*26];    // [oc pad26][chunk*8 + slot] u32 pairs

    const int b    = blockIdx.x / 112;
    const int pr   = blockIdx.x % 112;
    const int r0   = 2 * pr;
    const int tid  = threadIdx.x;
    const int lane = tid & 31;
    const int warp = tid >> 5;
    const int colbase = warp * 16;
    const int kb = lane & 3;
    const int qr = lane >> 2;

    // ---- weights: 64 oc x 24 pairs -> slots ----
    #pragma unroll
    for (int e = 0; e < 4; e++) {
        const int t = tid + 448*e;
        if (t < 1536) {
            const int oc = t / 24, p = t % 24;
            const int tap = p >> 1, h = p & 1;
            const int cq = p >> 3, q = p & 7;
            const int slot = cq*8 + (q & 3)*2 + (q >> 2);
            const float f0 = (tap < 9) ? w1[oc*27 + (2*h)*9 + tap] : 0.f;
            const float f1 = (tap < 9 && h == 0) ? w1[oc*27 + 9 + tap] : 0.f;
            s_w[oc*26 + slot] = pack_h2(f0, f1);
        }
    }
    // ---- halo zeros (cols 0, 225; rows 0..3; both h arrays) ----
    if (tid < 16) {
        const int h = tid & 1, rem = tid >> 1;
        const int row = rem >> 1, side = rem & 1;
        s_p[h*HOFF + row*232 + (side ? 225 : 0)] = 0;
    }

    // ---- input staging: 224 tasks (4 rows x 56 float4), pre-packed pairs ----
    if (tid < 224) {
        const int row = tid / 56, j = tid % 56;
        const int gr = r0 - 1 + row;
        float4 v0 = make_float4(0.f,0.f,0.f,0.f);
        float4 v1 = v0, v2 = v0;
        if (gr >= 0 && gr < 224) {
            const float* xb = x + (long)b * 3 * 224 * 224 + gr*224;
            v0 = *((const float4*)(xb            ) + j);
            v1 = *((const float4*)(xb + 224*224  ) + j);
            v2 = *((const float4*)(xb + 2*224*224) + j);
        }
        const int base = row*232 + 4*j + 1;
        s_p[base+0] = pack_h2(v0.x, v1.x);  s_p[HOFF+base+0] = pack_h2(v2.x, 0.f);
        s_p[base+1] = pack_h2(v0.y, v1.y);  s_p[HOFF+base+1] = pack_h2(v2.y, 0.f);
        s_p[base+2] = pack_h2(v0.z, v1.z);  s_p[HOFF+base+2] = pack_h2(v2.z, 0.f);
        s_p[base+3] = pack_h2(v0.w, v1.w);  s_p[HOFF+base+3] = pack_h2(v2.w, 0.f);
    }

    // ---- per-lane A offsets: offP[chunk][{q=kb, q=kb+4}] ----
    int offP[3][2];
    #pragma unroll
    for (int cq = 0; cq < 3; cq++)
        #pragma unroll
        for (int hp = 0; hp < 2; hp++) {
            const int p = cq*8 + kb + 4*hp;
            const int tap = p >> 1, h = p & 1;
            offP[cq][hp] = (tap < 9) ? h*HOFF + (tap/3)*232 + (tap%3) : 0;
        }

    __syncthreads();

    float c[2][8][4];
    #pragma unroll
    for (int mt = 0; mt < 2; mt++)
        #pragma unroll
        for (int n = 0; n < 8; n++)
            #pragma unroll
            for (int i = 0; i < 4; i++) c[mt][n][i] = 0.f;

    const int abase = colbase + qr;
    #pragma unroll
    for (int cq = 0; cq < 3; cq++) {
        uint32_t bf0[8], bf1[8];
        #pragma unroll
        for (int n = 0; n < 8; n++) {
            const uint2 bb = *(const uint2*)(s_w + (n*8 + qr)*26 + cq*8 + kb*2);
            bf0[n] = bb.x; bf1[n] = bb.y;
        }
        #pragma unroll
        for (int mt = 0; mt < 2; mt++) {
            const int base = mt*232 + abase;
            const uint32_t a0 = s_p[offP[cq][0] + base];
            const uint32_t a1 = s_p[offP[cq][0] + base + 8];
            const uint32_t a2 = s_p[offP[cq][1] + base];
            const uint32_t a3 = s_p[offP[cq][1] + base + 8];
            #pragma unroll
            for (int n = 0; n < 8; n++)
                mma_f16(c[mt][n], a0, a1, a2, a3, bf0[n], bf1[n]);
        }
    }

    // ---- epilogue: bias + leaky + pool2, pack (oc, oc+1) -> one u32 ----
    #pragma unroll
    for (int n = 0; n < 8; n++)
        #pragma unroll
        for (int half = 0; half < 2; half++) {
            float mj[2];
            #pragma unroll
            for (int j = 0; j < 2; j++) {
                const int i  = half*2 + j;
                const int oc = n*8 + 2*kb + j;
                const float bv = bias[oc];
                float u0 = c[0][n][i] + bv; u0 = (u0 > 0.f) ? u0 : 0.01f*u0;
                float u1 = c[1][n][i] + bv; u1 = (u1 > 0.f) ? u1 : 0.01f*u1;
                float m = fmaxf(u0, u1);
                m = fmaxf(m, __shfl_xor_sync(0xffffffffu, m, 4));
                mj[j] = m;
            }
            if ((qr & 1) == 0) {
                const int p  = colbase + qr + half*8;
                const int pc = p >> 1;
                outp[((long)(b*32 + n*4 + kb)*HB + pr)*HB + pc] = pack_h2(mj[0], mj[1]);
            }
        }
}

// ---------------------------------------------------------------------------
// conv2 (R13-exact): h1h -> h2. cp.async double-buffered, weights resident.
// ---------------------------------------------------------------------------
#define C2_WSIZE  (4*9*64*8)
#define C2_BSIZE  (6*8*120)
#define C2_SMEM_BYTES ((C2_WSIZE + 2*C2_BSIZE)*4)   // 119808 B

__global__ void __launch_bounds__(224, 1)
conv2_mma(const uint32_t* __restrict__ h1h,
          const float* __restrict__ w2,
          const float* __restrict__ bias,
          float* __restrict__ out)
{
    extern __shared__ uint32_t smem[];
    uint32_t* s_w = smem;
    uint32_t* s_b[2] = { smem + C2_WSIZE, smem + C2_WSIZE + C2_BSIZE };
    uint32_t sb_addr[2];
    sb_addr[0] = (uint32_t)__cvta_generic_to_shared(s_b[0]);
    sb_addr[1] = (uint32_t)__cvta_generic_to_shared(s_b[1]);

    const int b    = blockIdx.x / 28;
    const int prb  = blockIdx.x % 28;
    const int r0   = 4 * prb;
    const int tid  = threadIdx.x;
    const int lane = tid & 31;
    const int warp = tid >> 5;
    const int colbase = warp * 16;
    const int kb = lane & 3;
    const int qr = lane >> 2;

    const uint32_t* srcb = h1h + (long)b * 32 * HB * HB;

    int tq[6], trow[6], tp[6];
    #pragma unroll
    for (int it = 0; it < 6; it++) {
        const int t = tid + 224*it;
        tq[it] = t % 28; trow[it] = (t/28) % 6; tp[it] = t / 168;
    }

    #pragma unroll
    for (int ch = 0; ch < 2; ch++) {
        #pragma unroll
        for (int it = 0; it < 6; it++) {
            const int gr = r0 - 1 + trow[it];
            const uint32_t* src = (gr >= 0 && gr < HB)
                ? srcb + ((ch*8 + tp[it])*HB + gr)*HB + 4*tq[it] : g_zero;
            const uint32_t dst = sb_addr[ch] + (((trow[it]*8 + tp[it])*120 + 4*tq[it] + 4) << 2);
            CP_ASYNC16(dst, src);
        }
        CP_COMMIT();
    }

    if (tid < 96) {
        const int side = tid & 1, rp2 = tid >> 1;
        const int row = rp2 >> 3, p = rp2 & 7;
        const int idx = (row*8 + p)*120 + (side ? 116 : 3);
        s_b[0][idx] = 0; s_b[1][idx] = 0;
    }

    #pragma unroll
    for (int wt = 0; wt < 10; wt++) {
        const int t = tid + 224*wt;
        if (t < 2048) {
            const int oc = t >> 5, gp = t & 31;
            const int ch = gp >> 3, p = gp & 7;
            const int slot = (p & 3)*2 + (p >> 2);
            const float* we = w2 + (oc*64 + 2*gp    )*9;
            const float* wo = w2 + (oc*64 + 2*gp + 1)*9;
            float fe[9], fo[9];
            #pragma unroll
            for (int tp9 = 0; tp9 < 9; tp9++) { fe[tp9] = we[tp9]; fo[tp9] = wo[tp9]; }
            #pragma unroll
            for (int tp9 = 0; tp9 < 9; tp9++)
                s_w[((ch*9 + tp9)*64 + oc)*8 + slot] = pack_h2(fe[tp9], fo[tp9]);
        }
    }

    float c[4][8][4];
    #pragma unroll
    for (int mt = 0; mt < 4; mt++)
        #pragma unroll
        for (int n = 0; n < 8; n++)
            #pragma unroll
            for (int i = 0; i < 4; i++) c[mt][n][i] = 0.f;

    CP_WAIT(1);
    __syncthreads();

    for (int ch = 0; ch < 4; ch++) {
        const uint32_t* buf = s_b[ch & 1];
        const uint32_t* wch = s_w + ch * (9*64*8);

        #pragma unroll
        for (int tap = 0; tap < 9; tap++) {
            const int ky = tap / 3, kx = tap % 3;
            uint32_t bf0[8], bf1[8];
            #pragma unroll
            for (int n = 0; n < 8; n++) {
                const uint2 bb = *(const uint2*)(wch + ((tap*64 + n*8 + qr) << 3) + (kb << 1));
                bf0[n] = bb.x; bf1[n] = bb.y;
            }
            const int cc0 = colbase + qr + kx + 3;
            #pragma unroll
            for (int mt = 0; mt < 4; mt++) {
                const int irow = mt + ky;
                const uint32_t a0 = buf[(irow*8 + kb    )*120 + cc0];
                const uint32_t a1 = buf[(irow*8 + kb    )*120 + cc0 + 8];
                const uint32_t a2 = buf[(irow*8 + kb + 4)*120 + cc0];
                const uint32_t a3 = buf[(irow*8 + kb + 4)*120 + cc0 + 8];
                #pragma unroll
                for (int n = 0; n < 8; n++)
                    mma_f16(c[mt][n], a0, a1, a2, a3, bf0[n], bf1[n]);
            }
        }

        __syncthreads();
        if (ch + 2 < 4) {
            #pragma unroll
            for (int it = 0; it < 6; it++) {
                const int gr = r0 - 1 + trow[it];
                const uint32_t* src = (gr >= 0 && gr < HB)
                    ? srcb + (((ch+2)*8 + tp[it])*HB + gr)*HB + 4*tq[it] : g_zero;
                const uint32_t dst = sb_addr[ch & 1] + (((trow[it]*8 + tp[it])*120 + 4*tq[it] + 4) << 2);
                CP_ASYNC16(dst, src);
            }
            CP_COMMIT();
        }
        if (ch < 3) {
            if (ch + 2 < 4) { CP_WAIT(1); } else { CP_WAIT(0); }
            __syncthreads();
        }
    }

    const int por = 2*prb;
    #pragma unroll
    for (int n = 0; n < 8; n++)
        #pragma unroll
        for (int half = 0; half < 2; half++)
            #pragma unroll
            for (int j = 0; j < 2; j++) {
                const int i  = half*2 + j;
                const int oc = n*8 + 2*kb + j;
                const float bv = bias[oc];
                float u0 = c[0][n][i] + bv; u0 = (u0 > 0.f) ? u0 : 0.01f*u0;
                float u1 = c[1][n][i] + bv; u1 = (u1 > 0.f) ? u1 : 0.01f*u1;
                float u2 = c[2][n][i] + bv; u2 = (u2 > 0.f) ? u2 : 0.01f*u2;
                float u3 = c[3][n][i] + bv; u3 = (u3 > 0.f) ? u3 : 0.01f*u3;
                float m0 = fmaxf(u0, u1);
                float m1 = fmaxf(u2, u3);
                m0 = fmaxf(m0, __shfl_xor_sync(0xffffffffu, m0, 4));
                m1 = fmaxf(m1, __shfl_xor_sync(0xffffffffu, m1, 4));
                if ((qr & 1) == 0) {
                    const int p  = colbase + qr + half*8;
                    const int pc = p >> 1;
                    float* ob = out + ((long)(b*OCH + oc)*HC + por)*HC + pc;
                    ob[0]  = m0;
                    ob[HC] = m1;
                }
            }
}

// ---------------------------------------------------------------------------
// FC (R13-exact)
// ---------------------------------------------------------------------------
__global__ void fc_partial(const float* __restrict__ h,
                           const float* __restrict__ w,
                           float* __restrict__ part)
{
    const int chunk = blockIdx.x;
    const int bg    = blockIdx.y;
    const int tid   = threadIdx.x;
    const float* wp = w + (long)chunk * CHUNK * 10;
    const float* hp = h + (long)(bg*4) * FLATK + chunk * CHUNK;

    float acc[4][10];
    #pragma unroll
    for (int bb = 0; bb < 4; bb++)
        #pragma unroll
        for (int j = 0; j < 10; j++) acc[bb][j] = 0.f;

    #pragma unroll
    for (int it = 0; it < 8; it++) {
        const int k = tid + 256*it;
        float wr[10];
        #pragma unroll
        for (int j = 0; j < 10; j++) wr[j] = wp[k*10 + j];
        float hv[4];
        #pragma unroll
        for (int bb = 0; bb < 4; bb++) hv[bb] = hp[(long)bb*FLATK + k];
        #pragma unroll
        for (int bb = 0; bb < 4; bb++)
            #pragma unroll
            for (int j = 0; j < 10; j++)
                acc[bb][j] = fmaf(hv[bb], wr[j], acc[bb][j]);
    }

    #pragma unroll
    for (int bb = 0; bb < 4; bb++)
        #pragma unroll
        for (int j = 0; j < 10; j++)
            #pragma unroll
            for (int off = 16; off; off >>= 1)
                acc[bb][j] += __shfl_down_sync(0xffffffffu, acc[bb][j], off);

    __shared__ float sred[8][40];
    const int warp = tid >> 5, lane = tid & 31;
    if (lane == 0) {
        #pragma unroll
        for (int bb = 0; bb < 4; bb++)
            #pragma unroll
            for (int j = 0; j < 10; j++) sred[warp][bb*10 + j] = acc[bb][j];
    }
    __syncthreads();
    if (tid < 40) {
        float s = 0.f;
        #pragma unroll
        for (int w8 = 0; w8 < 8; w8++) s += sred[w8][tid];
        part[(chunk*8 + bg)*40 + tid] = s;
    }
}

__global__ void fc_combine(const float* __restrict__ part,
                           const float* __restrict__ bfc,
                           float* __restrict__ out)
{
    const int i = blockIdx.x * 64 + threadIdx.x;
    if (i >= NB * 10) return;
    const int b = i / 10, j = i % 10;
    const int bg = b >> 2, bb = b & 3;
    float s = bfc[j];
    for (int c = 0; c < NCHUNK; c++)
        s += part[(c*8 + bg)*40 + bb*10 + j];
    out[i] = s;
}

// ---------------------------------------------------------------------------
extern "C" void kernel_launch(void* const* d_in, const int* in_sizes, int n_in,
                              void* d_out, int out_size)
{
    const float* x   = (const float*)d_in[0];
    const float* w1  = (const float*)d_in[1];
    const float* b1  = (const float*)d_in[2];
    const float* w2  = (const float*)d_in[3];
    const float* b2  = (const float*)d_in[4];
    const float* wfc = (const float*)d_in[5];
    const float* bfc = (const float*)d_in[6];
    float* out = (float*)d_out;

    uint32_t* h1h; float *h2, *fcp;
    cudaGetSymbolAddress((void**)&h1h, g_h1h);
    cudaGetSymbolAddress((void**)&h2,  g_h2);
    cudaGetSymbolAddress((void**)&fcp, g_fcp);

    cudaFuncSetAttribute(conv2_mma, cudaFuncAttributeMaxDynamicSharedMemorySize,
                         C2_SMEM_BYTES);

    // steer ncu (captures 4th launch) onto conv1_mma
    nop_kernel<<<1, 32>>>();
    nop_kernel<<<1, 32>>>();
    nop_kernel<<<1, 32>>>();

    conv1_mma<<<NB * 112, 448>>>(x, w1, b1, h1h);
    conv2_mma<<<NB * 28, 224, C2_SMEM_BYTES>>>(h1h, w2, b2, h2);
    fc_partial<<<dim3(NCHUNK, 8), 256>>>(h2, wfc, fcp);
    fc_combine<<<5, 64>>>(fcp, bfc, out);
}